// round 10
// baseline (speedup 1.0000x reference)
#include <cuda_runtime.h>
#include <math.h>

// B=8, D=64, O=256, I=256, G=128
// Output: V(8) | A(8*65536) | hn(8*64) | cn(8*64)
#define OFF_V  0
#define OFF_A  8
#define OFF_HN 524296
#define OFF_CN 524808

// ---- scratch ----
__device__ float g_hn[8 * 64];
__device__ float g_M[4 * 128 * 64];     // m0=Wa1@Wo, m1=Wa1@Wi, m2=Wa1@Ws, m3=Wv1@Wv0
__device__ float g_bba[128];            // Wa1@ba0 + ba1
__device__ float g_bbv[128];            // Wv1@bv0 + bv1
__device__ float g_c1[128];
__device__ float g_c2d[256];
__device__ float g_vvT[8 * 128 * 256];  // [b][g][o]
__device__ float g_wT[8 * 128 * 256];   // [b][g][i]
__device__ float g_PQ[4096];

__device__ __forceinline__ float sigm(float x) { return 1.0f / (1.0f + expf(-x)); }

__device__ __forceinline__ float warp_sum(float v) {
    #pragma unroll
    for (int o = 16; o; o >>= 1) v += __shfl_xor_sync(0xffffffffu, v, o);
    return v;
}

__device__ __forceinline__ unsigned long long addp(unsigned long long a, unsigned long long b) {
    unsigned long long r;
    asm("add.rn.f32x2 %0, %1, %2;" : "=l"(r) : "l"(a), "l"(b));
    return r;
}
__device__ __forceinline__ unsigned long long fmap(unsigned long long a, unsigned long long b, unsigned long long c) {
    unsigned long long r;
    asm("fma.rn.f32x2 %0, %1, %2, %3;" : "=l"(r) : "l"(a), "l"(b), "l"(c));
    return r;
}

// ============================================================
// K1: blocks 0..31 : 4 GEMMs (Wa1@Wo, Wa1@Wi, Wa1@Ws, Wv1@Wv0)
//     block  32    : fused biases + c1/c2d
// dynamic smem 45120 B
// ============================================================
__global__ void __launch_bounds__(256) k_setup(
                        const float* __restrict__ Wv0, const float* __restrict__ bv0,
                        const float* __restrict__ Wv1, const float* __restrict__ bv1,
                        const float* __restrict__ Wa0, const float* __restrict__ ba0,
                        const float* __restrict__ Wa1, const float* __restrict__ ba1,
                        const float* __restrict__ Wa2)
{
    extern __shared__ float dsm[];
    const int t = threadIdx.x;

    if (blockIdx.x < 32) {
        float* sA = dsm;                 // 16*129
        float* sB = dsm + 16 * 129;      // 128*72
        const int m  = blockIdx.x >> 3;  // 0..3
        const int gc = blockIdx.x & 7;

        const float* Aglob = (m == 3) ? Wv1 : Wa1;
        #pragma unroll
        for (int i = 0; i < 8; i++) {
            int idx = t + i * 256;
            sA[(idx >> 7) * 129 + (idx & 127)] = Aglob[gc * 2048 + idx];
        }
        {
            int hh0 = t >> 4, c4 = t & 15;
            #pragma unroll
            for (int i = 0; i < 8; i++) {
                int hh = hh0 + i * 16;
                const float* src = (m == 3) ? (Wv0 + hh * 64)
                                            : (Wa0 + hh * 192 + ((m == 0) ? 64 : (m == 1) ? 128 : 0));
                float4 v = *(const float4*)(src + c4 * 4);
                *(float4*)(sB + hh * 72 + c4 * 4) = v;
            }
        }
        __syncthreads();

        const int g = t >> 4, dg = t & 15;
        float4 acc = make_float4(0.f, 0.f, 0.f, 0.f);
        const float* arow = sA + g * 129;
        const float* bcol = sB + dg * 4;
        #pragma unroll 8
        for (int hh = 0; hh < 128; hh++) {
            float a = arow[hh];
            float4 bv = *(const float4*)(bcol + hh * 72);
            acc.x += a * bv.x; acc.y += a * bv.y; acc.z += a * bv.z; acc.w += a * bv.w;
        }
        *(float4*)(g_M + m * 8192 + (gc * 16 + g) * 64 + dg * 4) = acc;
        return;
    }

    // bias block
    __shared__ float sb[256];
    if (t < 128) sb[t] = ba0[t];
    else         sb[t] = bv0[t - 128];
    __syncthreads();
    if (t < 128) {
        float acc = ba1[t];
        const float4* row = (const float4*)(Wa1 + t * 128);
        #pragma unroll 8
        for (int j = 0; j < 32; j++) {
            float4 w4 = row[j];
            float4 x4 = *(const float4*)(sb + j * 4);
            acc += w4.x * x4.x + w4.y * x4.y + w4.z * x4.z + w4.w * x4.w;
        }
        g_bba[t] = acc;
        float w2 = Wa2[t];
        g_c1[t] = 0.505f * w2;
        g_c2d[2 * t]     = 0.495f * w2;
        g_c2d[2 * t + 1] = 0.495f * w2;
    } else {
        int r = t - 128;
        float acc = bv1[r];
        const float4* row = (const float4*)(Wv1 + r * 128);
        #pragma unroll 8
        for (int j = 0; j < 32; j++) {
            float4 w4 = row[j];
            float4 x4 = *(const float4*)(sb + 128 + j * 4);
            acc += w4.x * x4.x + w4.y * x4.y + w4.z * x4.z + w4.w * x4.w;
        }
        g_bbv[r] = acc;
    }
}

// ============================================================
// K2: blocks 0..127 : vv/w rows (2 groups of 16 rows per block,
//                     256 threads) + fused P'/Q
//     blocks 128..135: per-batch mean / gates / LSTM -> g_hn, out
//                      (independent of K1)
// ============================================================
__global__ void __launch_bounds__(256) k_vw(const float* __restrict__ ope,
                                            const float* __restrict__ ins,
                                            const float* __restrict__ h_in,
                                            const float* __restrict__ c_in,
                                            const float* __restrict__ W_ih,
                                            const float* __restrict__ W_hh,
                                            const float* __restrict__ b_ih,
                                            const float* __restrict__ b_hh,
                                            float* __restrict__ out)
{
    const int t = threadIdx.x;

    if (blockIdx.x >= 128) {
        // ---- LSTM block for batch b ----
        __shared__ float sPart[1024];
        __shared__ float s_x[128];
        __shared__ float s_gates[256];
        const int b = blockIdx.x - 128;

        float4 wi[16];
        {
            const float4* pwi = (const float4*)(W_ih + t * 64);
            #pragma unroll
            for (int j = 0; j < 16; j++) wi[j] = pwi[j];
        }
        {
            int dq = t & 15, rc = t >> 4;
            const float* base = ope + (b * 258 + 1 + rc * 16) * 64 + dq * 4;
            float4 s = make_float4(0.f, 0.f, 0.f, 0.f);
            #pragma unroll
            for (int rr = 0; rr < 16; rr++) {
                float4 x = *(const float4*)(base + rr * 64);
                s.x += x.x; s.y += x.y; s.z += x.z; s.w += x.w;
            }
            *(float4*)(sPart + rc * 64 + dq * 4) = s;
        }
        if (t >= 64 && t < 128) s_x[t] = h_in[b * 64 + (t - 64)];
        __syncthreads();
        if (t < 64) {
            float s = 0.f;
            #pragma unroll
            for (int rc = 0; rc < 16; rc++) s += sPart[rc * 64 + t];
            s_x[t] = s * (1.0f / 256.0f);
        }
        __syncthreads();

        float acc = b_ih[t] + b_hh[t];
        #pragma unroll
        for (int j = 0; j < 16; j++) {
            float4 x4 = *(const float4*)(s_x + j * 4);
            acc += wi[j].x * x4.x + wi[j].y * x4.y + wi[j].z * x4.z + wi[j].w * x4.w;
        }
        {
            float4 wh[16];
            const float4* pwh = (const float4*)(W_hh + t * 64);
            #pragma unroll
            for (int j = 0; j < 16; j++) wh[j] = pwh[j];
            #pragma unroll
            for (int j = 0; j < 16; j++) {
                float4 x4 = *(const float4*)(s_x + 64 + j * 4);
                acc += wh[j].x * x4.x + wh[j].y * x4.y + wh[j].z * x4.z + wh[j].w * x4.w;
            }
        }
        s_gates[t] = acc;
        __syncthreads();

        if (t < 64) {
            float ig = sigm(s_gates[t]);
            float fg = sigm(s_gates[64 + t]);
            float gg = tanhf(s_gates[128 + t]);
            float og = sigm(s_gates[192 + t]);
            float cn = fg * c_in[b * 64 + t] + ig * gg;
            float hn = og * tanhf(cn);
            g_hn[b * 64 + t] = hn;
            out[OFF_HN + b * 64 + t] = hn;
            out[OFF_CN + b * 64 + t] = cn;
        }
        return;
    }

    // ---- main: 2 groups of 16 rows; group gi = t>>7, g = t&127 ----
    __shared__ float sIn[2][1024];
    __shared__ float sRed[2][2048];
    const int gi = t >> 7;
    const int g = t & 127;
    const int rbase = blockIdx.x * 32 + gi * 16;
    const bool isV = (rbase < 2048);
    const int rb = isV ? rbase : (rbase - 2048);
    const int b = rb >> 8;
    const int x0 = rb & 255;

    const float4* Mrow = (const float4*)(g_M + (isV ? 0 : 8192) + g * 64);
    float4 m[16];
    #pragma unroll
    for (int j = 0; j < 16; j++) m[j] = Mrow[j];

    const float4* s4 = (const float4*)(isV ? (ope + (b * 258 + 1 + x0) * 64)
                                           : (ins + (b * 256 + x0) * 64));
    ((float4*)sIn[gi])[g] = s4[g];
    ((float4*)sIn[gi])[g + 128] = s4[g + 128];

    const float c1 = g_c1[g];
    __syncthreads();

    float accs[16];
    #pragma unroll
    for (int r = 0; r < 16; r++) {
        float a = 0.f;
        const float4* ip = (const float4*)(sIn[gi] + r * 64);
        #pragma unroll
        for (int j = 0; j < 16; j++) {
            float4 x = ip[j];
            a += m[j].x * x.x + m[j].y * x.y + m[j].z * x.z + m[j].w * x.w;
        }
        accs[r] = a;
        sRed[gi][r * 128 + g] = c1 * a;
    }

    float* dst = (isV ? g_vvT : g_wT) + b * 32768 + g * 256 + x0;
    #pragma unroll
    for (int r4 = 0; r4 < 4; r4++)
        *(float4*)(dst + r4 * 4) = make_float4(accs[r4*4], accs[r4*4+1], accs[r4*4+2], accs[r4*4+3]);

    __syncthreads();
    int ww = g >> 5, lane = g & 31;
    #pragma unroll
    for (int rr = 0; rr < 4; rr++) {
        int row = ww * 4 + rr;
        float4 xx = ((const float4*)(sRed[gi] + row * 128))[lane];
        float s = xx.x + xx.y + xx.z + xx.w;
        #pragma unroll
        for (int off = 16; off; off >>= 1) s += __shfl_xor_sync(0xffffffffu, s, off);
        if (lane == 0) g_PQ[rbase + row] = s;
    }
}

// ============================================================
// K3: blocks 0..127 : A tiles (u + pc computed in staging)
//     blocks 128..135: V per batch
// dynamic smem 100864 B
// ============================================================
__global__ void __launch_bounds__(256) k_a(const float* __restrict__ ba2p,
                                           const float* __restrict__ Wv2,
                                           const float* __restrict__ bv2,
                                           float* __restrict__ out)
{
    extern __shared__ float sm[];
    const int bid = blockIdx.x;
    const int tid = threadIdx.x;

    if (bid >= 128) {
        // ---- V block ----
        __shared__ float shn2[64];
        __shared__ float sz[128];
        const int b = bid - 128;
        if (tid < 64) shn2[tid] = g_hn[b * 64 + tid];
        __syncthreads();
        if (tid < 128) {
            float acc = g_bbv[tid];
            const float4* row = (const float4*)(g_M + 3 * 8192 + tid * 64);
            #pragma unroll
            for (int j = 0; j < 16; j++) {
                float4 w4 = row[j];
                float4 x4 = *(const float4*)(shn2 + j * 4);
                acc += w4.x * x4.x + w4.y * x4.y + w4.z * x4.z + w4.w * x4.w;
            }
            sz[tid] = (acc >= 0.f) ? acc : 0.01f * acc;
        }
        __syncthreads();
        if (tid < 32) {
            float4 x = *(const float4*)(sz + tid * 4);
            float4 ww = *(const float4*)(Wv2 + tid * 4);
            float s = ww.x * x.x + ww.y * x.y + ww.z * x.z + ww.w * x.w;
            s = warp_sum(s);
            if (tid == 0) out[OFF_V + b] = s + bv2[0];
        }
        return;
    }

    float* sVd = sm;            // 16384
    float* sW  = sm + 16384;    // 8192
    float* sC2 = sm + 24576;    // 256
    float* sP  = sm + 24832;    // 64
    float* sQ  = sm + 24896;    // 64
    float* sU  = sm + 24960;    // 128
    float* sPc = sm + 25088;    // 4
    float* shn = sm + 25092;    // 64
    const int b = bid >> 4, oc = (bid >> 2) & 3, ic = bid & 3;

    const float* wsrc = g_wT  + b * 32768 + ic * 64;
    const float* vsrc = g_vvT + b * 32768 + oc * 64;

    // Phase A: stage sW + shn + sC2 + sP + sQ
    #pragma unroll
    for (int l = tid; l < 2048; l += 256) {
        int gg = l >> 4, q = (l & 15) << 2;
        float4 wv = *(const float4*)(wsrc + gg * 256 + q);
        *(float4*)(sW + gg * 64 + q) = wv;
    }
    sC2[tid] = g_c2d[tid & 255];
    if (tid < 64)        shn[tid] = g_hn[b * 64 + tid];
    else if (tid < 128)  sP[tid - 64] = g_PQ[b * 256 + oc * 64 + (tid - 64)];
    else if (tid < 192)  sQ[tid - 128] = g_PQ[2048 + b * 256 + ic * 64 + (tid - 128)];
    __syncthreads();

    // Phase B: u[g] = bba[g] + M2[g,:]·hn ; pc partials
    if (tid < 128) {
        float acc = g_bba[tid];
        const float4* row = (const float4*)(g_M + 2 * 8192 + tid * 64);
        #pragma unroll
        for (int j = 0; j < 16; j++) {
            float4 w4 = row[j];
            float4 x4 = *(const float4*)(shn + j * 4);
            acc += w4.x * x4.x + w4.y * x4.y + w4.z * x4.z + w4.w * x4.w;
        }
        sU[tid] = acc;
        float s = warp_sum(g_c1[tid] * acc);
        if ((tid & 31) == 0) sPc[tid >> 5] = s;
    }
    __syncthreads();

    // Phase C: stage sVd with u added, duplicated pairs
    #pragma unroll
    for (int l = tid; l < 2048; l += 256) {
        int gg = l >> 4, q = (l & 15) << 2;
        float uu = sU[gg];
        float4 vv = *(const float4*)(vsrc + gg * 256 + q);
        vv.x += uu; vv.y += uu; vv.z += uu; vv.w += uu;
        float* vd = sVd + gg * 128 + q * 2;
        ((float4*)vd)[0] = make_float4(vv.x, vv.x, vv.y, vv.y);
        ((float4*)vd)[1] = make_float4(vv.z, vv.z, vv.w, vv.w);
    }
    __syncthreads();

    const float pcb = sPc[0] + sPc[1] + sPc[2] + sPc[3] + ba2p[0];

    const int tx = tid & 15, ty = tid >> 4;
    unsigned long long a00 = 0, a01 = 0, a10 = 0, a11 = 0,
                       a20 = 0, a21 = 0, a30 = 0, a31 = 0;
    const float* vbase = sVd + ty * 8;
    const float* wbase = sW + tx * 4;
    const unsigned long long* c2base = (const unsigned long long*)sC2;
    const unsigned long long MASK = 0x7FFFFFFF7FFFFFFFULL;

    #pragma unroll 4
    for (int gg = 0; gg < 128; gg++) {
        ulonglong2 vp01 = *(const ulonglong2*)(vbase + gg * 128);
        ulonglong2 vp23 = *(const ulonglong2*)(vbase + gg * 128 + 4);
        ulonglong2 wp   = *(const ulonglong2*)(wbase + gg * 64);
        unsigned long long c2 = c2base[gg];
        unsigned long long t;
        t = addp(vp01.x, wp.x) & MASK;  a00 = fmap(c2, t, a00);
        t = addp(vp01.x, wp.y) & MASK;  a01 = fmap(c2, t, a01);
        t = addp(vp01.y, wp.x) & MASK;  a10 = fmap(c2, t, a10);
        t = addp(vp01.y, wp.y) & MASK;  a11 = fmap(c2, t, a11);
        t = addp(vp23.x, wp.x) & MASK;  a20 = fmap(c2, t, a20);
        t = addp(vp23.x, wp.y) & MASK;  a21 = fmap(c2, t, a21);
        t = addp(vp23.y, wp.x) & MASK;  a30 = fmap(c2, t, a30);
        t = addp(vp23.y, wp.y) & MASK;  a31 = fmap(c2, t, a31);
    }

    float4 q4 = *(const float4*)(sQ + tx * 4);
    unsigned long long acc[4][2] = {{a00,a01},{a10,a11},{a20,a21},{a30,a31}};
    #pragma unroll
    for (int r = 0; r < 4; r++) {
        float pr = sP[ty * 4 + r] + pcb;
        float4 res;
        res.x = __uint_as_float((unsigned)(acc[r][0] & 0xffffffffULL)) + pr + q4.x;
        res.y = __uint_as_float((unsigned)(acc[r][0] >> 32))           + pr + q4.y;
        res.z = __uint_as_float((unsigned)(acc[r][1] & 0xffffffffULL)) + pr + q4.z;
        res.w = __uint_as_float((unsigned)(acc[r][1] >> 32))           + pr + q4.w;
        int og = oc * 64 + ty * 4 + r;
        *(float4*)(out + OFF_A + b * 65536 + og * 256 + ic * 64 + tx * 4) = res;
    }
}

// ============================================================
extern "C" void kernel_launch(void* const* d_in, const int* in_sizes, int n_in,
                              void* d_out, int out_size)
{
    const float* ope   = (const float*)d_in[0];
    const float* ins   = (const float*)d_in[1];
    const float* h_in  = (const float*)d_in[2];
    const float* c_in  = (const float*)d_in[3];
    const float* W_ih  = (const float*)d_in[4];
    const float* W_hh  = (const float*)d_in[5];
    const float* b_ih  = (const float*)d_in[6];
    const float* b_hh  = (const float*)d_in[7];
    const float* Wv0   = (const float*)d_in[8];
    const float* bv0   = (const float*)d_in[9];
    const float* Wv1   = (const float*)d_in[10];
    const float* bv1   = (const float*)d_in[11];
    const float* Wv2   = (const float*)d_in[12];
    const float* bv2   = (const float*)d_in[13];
    const float* Wa0   = (const float*)d_in[14];
    const float* ba0   = (const float*)d_in[15];
    const float* Wa1   = (const float*)d_in[16];
    const float* ba1   = (const float*)d_in[17];
    const float* Wa2   = (const float*)d_in[18];
    const float* ba2   = (const float*)d_in[19];
    float* out = (float*)d_out;

    cudaFuncSetAttribute(k_setup, cudaFuncAttributeMaxDynamicSharedMemorySize, 46080);
    cudaFuncSetAttribute(k_a, cudaFuncAttributeMaxDynamicSharedMemorySize, 100864);

    k_setup<<<33, 256, 45120>>>(Wv0, bv0, Wv1, bv1, Wa0, ba0, Wa1, ba1, Wa2);
    k_vw<<<136, 256>>>(ope, ins, h_in, c_in, W_ih, W_hh, b_ih, b_hh, out);
    k_a<<<136, 256, 100864>>>(ba2, Wv2, bv2, out);
}

// round 11
// speedup vs baseline: 1.0417x; 1.0417x over previous
#include <cuda_runtime.h>
#include <math.h>

// B=8, D=64, O=256, I=256, G=128
// Output: V(8) | A(8*65536) | hn(8*64) | cn(8*64)
#define OFF_V  0
#define OFF_A  8
#define OFF_HN 524296
#define OFF_CN 524808

#define NBLK 136

// ---- scratch ----
__device__ float g_hn[8 * 64];
__device__ float g_u[8 * 128];
__device__ float g_pc[8];
__device__ float g_M[4 * 128 * 64];     // m0=Wa1@Wo, m1=Wa1@Wi, m2=Wa1@Ws, m3=Wv1@Wv0
__device__ float g_bba[128];
__device__ float g_bbv[128];
__device__ float g_c1[128];
__device__ float g_c2d[256];
__device__ float g_vvT[8 * 128 * 256];  // [b][g][o]
__device__ float g_wT[8 * 128 * 256];   // [b][g][i]
__device__ float g_PQ[4096];

// ---- grid barrier (generation counter; replay-safe) ----
__device__ unsigned g_barcnt = 0;
__device__ volatile unsigned g_bargen = 0;

__device__ __forceinline__ void grid_barrier() {
    __syncthreads();
    if (threadIdx.x == 0) {
        __threadfence();
        unsigned gen = g_bargen;
        if (atomicAdd(&g_barcnt, 1) == (unsigned)(gridDim.x - 1)) {
            g_barcnt = 0;
            __threadfence();
            g_bargen = gen + 1;
        } else {
            while (g_bargen == gen) { __nanosleep(32); }
        }
        __threadfence();
    }
    __syncthreads();
}

__device__ __forceinline__ float sigm(float x) { return 1.0f / (1.0f + expf(-x)); }

__device__ __forceinline__ float warp_sum(float v) {
    #pragma unroll
    for (int o = 16; o; o >>= 1) v += __shfl_xor_sync(0xffffffffu, v, o);
    return v;
}

__device__ __forceinline__ unsigned long long addp(unsigned long long a, unsigned long long b) {
    unsigned long long r;
    asm("add.rn.f32x2 %0, %1, %2;" : "=l"(r) : "l"(a), "l"(b));
    return r;
}
__device__ __forceinline__ unsigned long long fmap(unsigned long long a, unsigned long long b, unsigned long long c) {
    unsigned long long r;
    asm("fma.rn.f32x2 %0, %1, %2, %3;" : "=l"(r) : "l"(a), "l"(b), "l"(c));
    return r;
}

// ============================================================
// One persistent kernel. 136 blocks x 256 threads, 99840 B dsm.
// P1: GEMMs(0-31) | bias(32) | LSTM(33-40) | idle(41-135)
// P2: vv/w main 2-group (0-127) | u/pc/V (128-135)
// P3: A tiles (0-127) | idle (128-135)
// ============================================================
__global__ void __launch_bounds__(256) k_all(
        const float* __restrict__ ope,  const float* __restrict__ ins,
        const float* __restrict__ h_in, const float* __restrict__ c_in,
        const float* __restrict__ W_ih, const float* __restrict__ W_hh,
        const float* __restrict__ b_ih, const float* __restrict__ b_hh,
        const float* __restrict__ Wv0,  const float* __restrict__ bv0,
        const float* __restrict__ Wv1,  const float* __restrict__ bv1,
        const float* __restrict__ Wv2,  const float* __restrict__ bv2,
        const float* __restrict__ Wa0,  const float* __restrict__ ba0,
        const float* __restrict__ Wa1,  const float* __restrict__ ba1,
        const float* __restrict__ Wa2,  const float* __restrict__ ba2p,
        float* __restrict__ out)
{
    extern __shared__ float dsm[];
    const int bid = blockIdx.x;
    const int t = threadIdx.x;

    // ================= PHASE 1 =================
    if (bid < 32) {
        float* sA = dsm;                 // 16*129
        float* sB = dsm + 16 * 129;      // 128*72
        const int m  = bid >> 3;
        const int gc = bid & 7;

        const float* Aglob = (m == 3) ? Wv1 : Wa1;
        #pragma unroll
        for (int i = 0; i < 8; i++) {
            int idx = t + i * 256;
            sA[(idx >> 7) * 129 + (idx & 127)] = Aglob[gc * 2048 + idx];
        }
        {
            int hh0 = t >> 4, c4 = t & 15;
            #pragma unroll
            for (int i = 0; i < 8; i++) {
                int hh = hh0 + i * 16;
                const float* src = (m == 3) ? (Wv0 + hh * 64)
                                            : (Wa0 + hh * 192 + ((m == 0) ? 64 : (m == 1) ? 128 : 0));
                float4 v = *(const float4*)(src + c4 * 4);
                *(float4*)(sB + hh * 72 + c4 * 4) = v;
            }
        }
        __syncthreads();

        const int g = t >> 4, dg = t & 15;
        float4 acc = make_float4(0.f, 0.f, 0.f, 0.f);
        const float* arow = sA + g * 129;
        const float* bcol = sB + dg * 4;
        #pragma unroll 8
        for (int hh = 0; hh < 128; hh++) {
            float a = arow[hh];
            float4 bv = *(const float4*)(bcol + hh * 72);
            acc.x += a * bv.x; acc.y += a * bv.y; acc.z += a * bv.z; acc.w += a * bv.w;
        }
        *(float4*)(g_M + m * 8192 + (gc * 16 + g) * 64 + dg * 4) = acc;
    }
    else if (bid == 32) {
        __shared__ float sb[256];
        if (t < 128) sb[t] = ba0[t];
        else         sb[t] = bv0[t - 128];
        __syncthreads();
        if (t < 128) {
            float acc = ba1[t];
            const float4* row = (const float4*)(Wa1 + t * 128);
            #pragma unroll 8
            for (int j = 0; j < 32; j++) {
                float4 w4 = row[j];
                float4 x4 = *(const float4*)(sb + j * 4);
                acc += w4.x * x4.x + w4.y * x4.y + w4.z * x4.z + w4.w * x4.w;
            }
            g_bba[t] = acc;
            float w2 = Wa2[t];
            g_c1[t] = 0.505f * w2;
            g_c2d[2 * t]     = 0.495f * w2;
            g_c2d[2 * t + 1] = 0.495f * w2;
        } else {
            int r = t - 128;
            float acc = bv1[r];
            const float4* row = (const float4*)(Wv1 + r * 128);
            #pragma unroll 8
            for (int j = 0; j < 32; j++) {
                float4 w4 = row[j];
                float4 x4 = *(const float4*)(sb + 128 + j * 4);
                acc += w4.x * x4.x + w4.y * x4.y + w4.z * x4.z + w4.w * x4.w;
            }
            g_bbv[r] = acc;
        }
    }
    else if (bid < 41) {
        // per-batch mean / gates (register weights) / LSTM
        __shared__ float sPart[1024];
        __shared__ float s_x[128];
        __shared__ float s_gates[256];
        const int b = bid - 33;

        float4 wi[16];
        {
            const float4* pwi = (const float4*)(W_ih + t * 64);
            #pragma unroll
            for (int j = 0; j < 16; j++) wi[j] = pwi[j];
        }
        {
            int dq = t & 15, rc = t >> 4;
            const float* base = ope + (b * 258 + 1 + rc * 16) * 64 + dq * 4;
            float4 s = make_float4(0.f, 0.f, 0.f, 0.f);
            #pragma unroll
            for (int rr = 0; rr < 16; rr++) {
                float4 x = *(const float4*)(base + rr * 64);
                s.x += x.x; s.y += x.y; s.z += x.z; s.w += x.w;
            }
            *(float4*)(sPart + rc * 64 + dq * 4) = s;
        }
        if (t >= 64 && t < 128) s_x[t] = h_in[b * 64 + (t - 64)];
        __syncthreads();
        if (t < 64) {
            float s = 0.f;
            #pragma unroll
            for (int rc = 0; rc < 16; rc++) s += sPart[rc * 64 + t];
            s_x[t] = s * (1.0f / 256.0f);
        }
        __syncthreads();

        float acc = b_ih[t] + b_hh[t];
        #pragma unroll
        for (int j = 0; j < 16; j++) {
            float4 x4 = *(const float4*)(s_x + j * 4);
            acc += wi[j].x * x4.x + wi[j].y * x4.y + wi[j].z * x4.z + wi[j].w * x4.w;
        }
        {
            float4 wh[16];
            const float4* pwh = (const float4*)(W_hh + t * 64);
            #pragma unroll
            for (int j = 0; j < 16; j++) wh[j] = pwh[j];
            #pragma unroll
            for (int j = 0; j < 16; j++) {
                float4 x4 = *(const float4*)(s_x + 64 + j * 4);
                acc += wh[j].x * x4.x + wh[j].y * x4.y + wh[j].z * x4.z + wh[j].w * x4.w;
            }
        }
        s_gates[t] = acc;
        __syncthreads();

        if (t < 64) {
            float ig = sigm(s_gates[t]);
            float fg = sigm(s_gates[64 + t]);
            float gg = tanhf(s_gates[128 + t]);
            float og = sigm(s_gates[192 + t]);
            float cn = fg * c_in[b * 64 + t] + ig * gg;
            float hn = og * tanhf(cn);
            g_hn[b * 64 + t] = hn;
            out[OFF_HN + b * 64 + t] = hn;
            out[OFF_CN + b * 64 + t] = cn;
        }
    }
    // blocks 41..135: straight to barrier (NO prefetch)

    grid_barrier();

    // ================= PHASE 2 =================
    if (bid < 128) {
        // two 16-row groups per block; gi = t>>7
        float* sIn  = dsm + (t >> 7) * 1024;          // per-group 1024
        float* sRed = dsm + 2048 + (t >> 7) * 2048;   // per-group 2048
        const int gi = t >> 7;
        const int g = t & 127;
        const int rbase = bid * 32 + gi * 16;
        const bool isV = (rbase < 2048);
        const int rb = isV ? rbase : (rbase - 2048);
        const int b = rb >> 8;
        const int x0 = rb & 255;

        const float4* Mrow = (const float4*)(g_M + (isV ? 0 : 8192) + g * 64);
        float4 m[16];
        #pragma unroll
        for (int j = 0; j < 16; j++) m[j] = Mrow[j];

        const float4* s4 = (const float4*)(isV ? (ope + (b * 258 + 1 + x0) * 64)
                                               : (ins + (b * 256 + x0) * 64));
        ((float4*)sIn)[g] = s4[g];
        ((float4*)sIn)[g + 128] = s4[g + 128];

        const float c1 = g_c1[g];
        __syncthreads();

        float accs[16];
        #pragma unroll
        for (int r = 0; r < 16; r++) {
            float a = 0.f;
            const float4* ip = (const float4*)(sIn + r * 64);
            #pragma unroll
            for (int j = 0; j < 16; j++) {
                float4 x = ip[j];
                a += m[j].x * x.x + m[j].y * x.y + m[j].z * x.z + m[j].w * x.w;
            }
            accs[r] = a;
            sRed[r * 128 + g] = c1 * a;
        }

        float* dst = (isV ? g_vvT : g_wT) + b * 32768 + g * 256 + x0;
        #pragma unroll
        for (int r4 = 0; r4 < 4; r4++)
            *(float4*)(dst + r4 * 4) = make_float4(accs[r4*4], accs[r4*4+1], accs[r4*4+2], accs[r4*4+3]);

        __syncthreads();
        int ww = g >> 5, lane = g & 31;
        #pragma unroll
        for (int rr = 0; rr < 4; rr++) {
            int row = ww * 4 + rr;
            float4 xx = ((const float4*)(sRed + row * 128))[lane];
            float s = xx.x + xx.y + xx.z + xx.w;
            #pragma unroll
            for (int off = 16; off; off >>= 1) s += __shfl_xor_sync(0xffffffffu, s, off);
            if (lane == 0) g_PQ[rbase + row] = s;
        }
    }
    else {
        // ---- u / pc / V per batch ----
        __shared__ float shn[64];
        __shared__ float spc[128];
        __shared__ float sz[128];
        const int b = bid - 128;
        if (t < 64) shn[t] = g_hn[b * 64 + t];
        __syncthreads();
        if (t < 128) {
            {
                float acc = g_bba[t];
                const float4* row = (const float4*)(g_M + 2 * 8192 + t * 64);
                #pragma unroll
                for (int j = 0; j < 16; j++) {
                    float4 w4 = row[j];
                    float4 x4 = *(const float4*)(shn + j * 4);
                    acc += w4.x * x4.x + w4.y * x4.y + w4.z * x4.z + w4.w * x4.w;
                }
                g_u[b * 128 + t] = acc;
                spc[t] = g_c1[t] * acc;
            }
            {
                float acc = g_bbv[t];
                const float4* row = (const float4*)(g_M + 3 * 8192 + t * 64);
                #pragma unroll
                for (int j = 0; j < 16; j++) {
                    float4 w4 = row[j];
                    float4 x4 = *(const float4*)(shn + j * 4);
                    acc += w4.x * x4.x + w4.y * x4.y + w4.z * x4.z + w4.w * x4.w;
                }
                sz[t] = (acc >= 0.f) ? acc : 0.01f * acc;
            }
        }
        __syncthreads();
        int w = t >> 5, lane = t & 31;
        if (w == 0) {
            float4 x = *(const float4*)(spc + lane * 4);
            float s = x.x + x.y + x.z + x.w;
            s = warp_sum(s);
            if (lane == 0) g_pc[b] = s;
        } else if (w == 1) {
            float4 x = *(const float4*)(sz + lane * 4);
            float4 ww = *(const float4*)(Wv2 + lane * 4);
            float s = ww.x * x.x + ww.y * x.y + ww.z * x.z + ww.w * x.w;
            s = warp_sum(s);
            if (lane == 0) out[OFF_V + b] = s + bv2[0];
        }
    }

    grid_barrier();

    // ================= PHASE 3 (A tiles, R6 k_a verbatim) =================
    if (bid < 128) {
        float* sVd = dsm;            // 16384
        float* sW  = dsm + 16384;    // 8192
        float* sC2 = dsm + 24576;    // 256
        float* sP  = dsm + 24832;    // 64
        float* sQ  = dsm + 24896;    // 64
        const int b = bid >> 4, oc = (bid >> 2) & 3, ic = bid & 3;
        const int tid = t;

        const float pcb = g_pc[b] + ba2p[0];

        const float* vsrc = g_vvT + b * 32768 + oc * 64;
        const float* wsrc = g_wT  + b * 32768 + ic * 64;
        const float* usrc = g_u + b * 128;
        #pragma unroll
        for (int l = tid; l < 2048; l += 256) {
            int gg = l >> 4, q = (l & 15) << 2;
            float4 wv = *(const float4*)(wsrc + gg * 256 + q);
            *(float4*)(sW + gg * 64 + q) = wv;
            float uu = usrc[gg];
            float4 vv = *(const float4*)(vsrc + gg * 256 + q);
            vv.x += uu; vv.y += uu; vv.z += uu; vv.w += uu;
            float* vd = sVd + gg * 128 + q * 2;
            ((float4*)vd)[0] = make_float4(vv.x, vv.x, vv.y, vv.y);
            ((float4*)vd)[1] = make_float4(vv.z, vv.z, vv.w, vv.w);
        }
        sC2[tid] = g_c2d[tid & 255];
        if (tid < 64)       sP[tid] = g_PQ[b * 256 + oc * 64 + tid];
        else if (tid < 128) sQ[tid - 64] = g_PQ[2048 + b * 256 + ic * 64 + (tid - 64)];
        __syncthreads();

        const int tx = tid & 15, ty = tid >> 4;
        unsigned long long a00 = 0, a01 = 0, a10 = 0, a11 = 0,
                           a20 = 0, a21 = 0, a30 = 0, a31 = 0;
        const float* vbase = sVd + ty * 8;
        const float* wbase = sW + tx * 4;
        const unsigned long long* c2base = (const unsigned long long*)sC2;
        const unsigned long long MASK = 0x7FFFFFFF7FFFFFFFULL;

        #pragma unroll 4
        for (int gg = 0; gg < 128; gg++) {
            ulonglong2 vp01 = *(const ulonglong2*)(vbase + gg * 128);
            ulonglong2 vp23 = *(const ulonglong2*)(vbase + gg * 128 + 4);
            ulonglong2 wp   = *(const ulonglong2*)(wbase + gg * 64);
            unsigned long long c2 = c2base[gg];
            unsigned long long tt;
            tt = addp(vp01.x, wp.x) & MASK;  a00 = fmap(c2, tt, a00);
            tt = addp(vp01.x, wp.y) & MASK;  a01 = fmap(c2, tt, a01);
            tt = addp(vp01.y, wp.x) & MASK;  a10 = fmap(c2, tt, a10);
            tt = addp(vp01.y, wp.y) & MASK;  a11 = fmap(c2, tt, a11);
            tt = addp(vp23.x, wp.x) & MASK;  a20 = fmap(c2, tt, a20);
            tt = addp(vp23.x, wp.y) & MASK;  a21 = fmap(c2, tt, a21);
            tt = addp(vp23.y, wp.x) & MASK;  a30 = fmap(c2, tt, a30);
            tt = addp(vp23.y, wp.y) & MASK;  a31 = fmap(c2, tt, a31);
        }

        float4 q4 = *(const float4*)(sQ + tx * 4);
        unsigned long long acc[4][2] = {{a00,a01},{a10,a11},{a20,a21},{a30,a31}};
        #pragma unroll
        for (int r = 0; r < 4; r++) {
            float pr = sP[ty * 4 + r] + pcb;
            float4 res;
            res.x = __uint_as_float((unsigned)(acc[r][0] & 0xffffffffULL)) + pr + q4.x;
            res.y = __uint_as_float((unsigned)(acc[r][0] >> 32))           + pr + q4.y;
            res.z = __uint_as_float((unsigned)(acc[r][1] & 0xffffffffULL)) + pr + q4.z;
            res.w = __uint_as_float((unsigned)(acc[r][1] >> 32))           + pr + q4.w;
            int og = oc * 64 + ty * 4 + r;
            *(float4*)(out + OFF_A + b * 65536 + og * 256 + ic * 64 + tx * 4) = res;
        }
    }
}

// ============================================================
extern "C" void kernel_launch(void* const* d_in, const int* in_sizes, int n_in,
                              void* d_out, int out_size)
{
    const float* ope   = (const float*)d_in[0];
    const float* ins   = (const float*)d_in[1];
    const float* h_in  = (const float*)d_in[2];
    const float* c_in  = (const float*)d_in[3];
    const float* W_ih  = (const float*)d_in[4];
    const float* W_hh  = (const float*)d_in[5];
    const float* b_ih  = (const float*)d_in[6];
    const float* b_hh  = (const float*)d_in[7];
    const float* Wv0   = (const float*)d_in[8];
    const float* bv0   = (const float*)d_in[9];
    const float* Wv1   = (const float*)d_in[10];
    const float* bv1   = (const float*)d_in[11];
    const float* Wv2   = (const float*)d_in[12];
    const float* bv2   = (const float*)d_in[13];
    const float* Wa0   = (const float*)d_in[14];
    const float* ba0   = (const float*)d_in[15];
    const float* Wa1   = (const float*)d_in[16];
    const float* ba1   = (const float*)d_in[17];
    const float* Wa2   = (const float*)d_in[18];
    const float* ba2   = (const float*)d_in[19];
    float* out = (float*)d_out;

    cudaFuncSetAttribute(k_all, cudaFuncAttributeMaxDynamicSharedMemorySize, 99840);

    k_all<<<NBLK, 256, 99840>>>(ope, ins, h_in, c_in, W_ih, W_hh, b_ih, b_hh,
                                Wv0, bv0, Wv1, bv1, Wv2, bv2,
                                Wa0, ba0, Wa1, ba1, Wa2, ba2, out);
}

// round 12
// speedup vs baseline: 1.1251x; 1.0801x over previous
#include <cuda_runtime.h>
#include <math.h>

// B=8, D=64, O=256, I=256, G=128
// Output: V(8) | A(8*65536) | hn(8*64) | cn(8*64)
#define OFF_V  0
#define OFF_A  8
#define OFF_HN 524296
#define OFF_CN 524808

// ---- scratch ----
__device__ float g_hn[8 * 64];
__device__ float g_M2[128 * 64];        // Wa1@Ws
__device__ float g_bba[128];            // Wa1@ba0 + ba1
__device__ float g_c1[128];
__device__ float g_c2d[256];
__device__ float g_vvT[8 * 128 * 256];  // [b][g][o]  (raw, no u)
__device__ float g_wT[8 * 128 * 256];   // [b][g][i]

__device__ __forceinline__ float sigm(float x) { return 1.0f / (1.0f + expf(-x)); }

__device__ __forceinline__ float warp_sum(float v) {
    #pragma unroll
    for (int o = 16; o; o >>= 1) v += __shfl_xor_sync(0xffffffffu, v, o);
    return v;
}

__device__ __forceinline__ unsigned long long addp(unsigned long long a, unsigned long long b) {
    unsigned long long r;
    asm("add.rn.f32x2 %0, %1, %2;" : "=l"(r) : "l"(a), "l"(b));
    return r;
}
__device__ __forceinline__ unsigned long long fmap(unsigned long long a, unsigned long long b, unsigned long long c) {
    unsigned long long r;
    asm("fma.rn.f32x2 %0, %1, %2, %3;" : "=l"(r) : "l"(a), "l"(b), "l"(c));
    return r;
}

// ============================================================
// KA (producer), 145 blocks x 256 thr, dsm 49472 B.
//  bid 0..127 : vv/w block (m = bid>>6, b = (bid>>3)&7, gc = bid&7):
//               in-block M-chunk GEMM then 16 g-rows x 256 x.
//  bid 128..135: LSTM per batch.
//  bid 136..143: M2 chunk gc.
//  bid 144     : bias (bba, c1, c2d).
// ============================================================
__global__ void __launch_bounds__(256) k_prod(
        const float* __restrict__ ope,  const float* __restrict__ ins,
        const float* __restrict__ h_in, const float* __restrict__ c_in,
        const float* __restrict__ W_ih, const float* __restrict__ W_hh,
        const float* __restrict__ b_ih, const float* __restrict__ b_hh,
        const float* __restrict__ Wa0,  const float* __restrict__ ba0,
        const float* __restrict__ Wa1,  const float* __restrict__ ba1,
        const float* __restrict__ Wa2,
        float* __restrict__ out)
{
    extern __shared__ float dsm[];
    const int bid = blockIdx.x;
    const int t = threadIdx.x;

    if (bid < 128 || (bid >= 136 && bid < 144)) {
        // ---- GEMM-based block ----
        const bool isM2 = (bid >= 136);
        const int m  = isM2 ? 2 : (bid >> 6);
        const int b  = isM2 ? 0 : ((bid >> 3) & 7);
        const int gc = isM2 ? (bid - 136) : (bid & 7);

        float* sA = dsm;              // 16*129 = 2064
        float* sB = dsm + 2064;       // 128*72 = 9216 (ends 11280)
        float* sM = dsm + 11280;      // 16*68  = 1088 (ends 12368)
        float* sIn = dsm;             // reuse [0..8192) after GEMM

        // stage A: Wa1 rows [gc*16, +16)
        #pragma unroll
        for (int i = 0; i < 8; i++) {
            int idx = t + i * 256;
            sA[(idx >> 7) * 129 + (idx & 127)] = Wa1[gc * 2048 + idx];
        }
        // stage B: Wa0 column slice (m0: +64, m1: +128, m2: +0)
        const int coff = (m == 2) ? 0 : (64 + m * 64);
        {
            int hh0 = t >> 4, c4 = t & 15;
            #pragma unroll
            for (int i = 0; i < 8; i++) {
                int hh = hh0 + i * 16;
                float4 v = *(const float4*)(Wa0 + hh * 192 + coff + c4 * 4);
                *(float4*)(sB + hh * 72 + c4 * 4) = v;
            }
        }
        __syncthreads();

        // M-chunk GEMM: 16 x 64, K=128
        {
            const int g = t >> 4, dg = t & 15;
            float4 acc = make_float4(0.f, 0.f, 0.f, 0.f);
            const float* ar = sA + g * 129;
            const float* bc = sB + dg * 4;
            #pragma unroll 8
            for (int hh = 0; hh < 128; hh++) {
                float a = ar[hh];
                float4 bv = *(const float4*)(bc + hh * 72);
                acc.x += a * bv.x; acc.y += a * bv.y; acc.z += a * bv.z; acc.w += a * bv.w;
            }
            *(float4*)(sM + g * 68 + dg * 4) = acc;
        }
        __syncthreads();

        if (isM2) {
            const int g = t >> 4, dg = t & 15;
            *(float4*)(g_M2 + (gc * 16 + g) * 64 + dg * 4) =
                *(const float4*)(sM + g * 68 + dg * 4);
            return;
        }

        // vv/w compute: thread = (xg = t>>4, g = t&15); M row in registers
        const int g = t & 15, xg = t >> 4;
        float4 mr[16];
        #pragma unroll
        for (int j = 0; j < 16; j++) mr[j] = *(const float4*)(sM + g * 68 + 4 * j);

        const float* src = (m == 0) ? (ope + (b * 258 + 1) * 64)
                                    : (ins + b * 256 * 64);
        float* dst = ((m == 0) ? g_vvT : g_wT) + b * 32768 + (gc * 16 + g) * 256;

        for (int ch = 0; ch < 2; ch++) {
            __syncthreads();  // protects sIn region reuse between chunks
            const float4* g4 = (const float4*)(src + ch * 128 * 64);
            #pragma unroll
            for (int k = 0; k < 8; k++)
                ((float4*)sIn)[t + k * 256] = g4[t + k * 256];
            __syncthreads();

            float accs[8];
            #pragma unroll
            for (int r = 0; r < 8; r++) {
                const float4* ip = (const float4*)(sIn + (xg * 8 + r) * 64);
                float a = 0.f;
                #pragma unroll
                for (int j = 0; j < 16; j++) {
                    float4 x = ip[j];
                    a += mr[j].x * x.x + mr[j].y * x.y + mr[j].z * x.z + mr[j].w * x.w;
                }
                accs[r] = a;
            }
            float* dp = dst + ch * 128 + xg * 8;
            *(float4*)(dp)     = make_float4(accs[0], accs[1], accs[2], accs[3]);
            *(float4*)(dp + 4) = make_float4(accs[4], accs[5], accs[6], accs[7]);
        }
        return;
    }

    if (bid == 144) {
        // ---- bias block: bba, c1, c2d ----
        __shared__ float sb[128];
        if (t < 128) sb[t] = ba0[t];
        __syncthreads();
        if (t < 128) {
            float acc = ba1[t];
            const float4* row = (const float4*)(Wa1 + t * 128);
            #pragma unroll 8
            for (int j = 0; j < 32; j++) {
                float4 w4 = row[j];
                float4 x4 = *(const float4*)(sb + j * 4);
                acc += w4.x * x4.x + w4.y * x4.y + w4.z * x4.z + w4.w * x4.w;
            }
            g_bba[t] = acc;
            float w2 = Wa2[t];
            g_c1[t] = 0.505f * w2;
            g_c2d[2 * t]     = 0.495f * w2;
            g_c2d[2 * t + 1] = 0.495f * w2;
        }
        return;
    }

    // ---- LSTM block (bid 128..135) ----
    {
        __shared__ float sPart[1024];
        __shared__ float s_x[128];
        __shared__ float s_gates[256];
        const int b = bid - 128;

        float4 wi[16];
        {
            const float4* pwi = (const float4*)(W_ih + t * 64);
            #pragma unroll
            for (int j = 0; j < 16; j++) wi[j] = pwi[j];
        }
        {
            int dq = t & 15, rc = t >> 4;
            const float* base = ope + (b * 258 + 1 + rc * 16) * 64 + dq * 4;
            float4 s = make_float4(0.f, 0.f, 0.f, 0.f);
            #pragma unroll
            for (int rr = 0; rr < 16; rr++) {
                float4 x = *(const float4*)(base + rr * 64);
                s.x += x.x; s.y += x.y; s.z += x.z; s.w += x.w;
            }
            *(float4*)(sPart + rc * 64 + dq * 4) = s;
        }
        if (t >= 64 && t < 128) s_x[t] = h_in[b * 64 + (t - 64)];
        __syncthreads();
        if (t < 64) {
            float s = 0.f;
            #pragma unroll
            for (int rc = 0; rc < 16; rc++) s += sPart[rc * 64 + t];
            s_x[t] = s * (1.0f / 256.0f);
        }
        __syncthreads();

        float acc = b_ih[t] + b_hh[t];
        #pragma unroll
        for (int j = 0; j < 16; j++) {
            float4 x4 = *(const float4*)(s_x + j * 4);
            acc += wi[j].x * x4.x + wi[j].y * x4.y + wi[j].z * x4.z + wi[j].w * x4.w;
        }
        {
            float4 wh[16];
            const float4* pwh = (const float4*)(W_hh + t * 64);
            #pragma unroll
            for (int j = 0; j < 16; j++) wh[j] = pwh[j];
            #pragma unroll
            for (int j = 0; j < 16; j++) {
                float4 x4 = *(const float4*)(s_x + 64 + j * 4);
                acc += wh[j].x * x4.x + wh[j].y * x4.y + wh[j].z * x4.z + wh[j].w * x4.w;
            }
        }
        s_gates[t] = acc;
        __syncthreads();

        if (t < 64) {
            float ig = sigm(s_gates[t]);
            float fg = sigm(s_gates[64 + t]);
            float gg = tanhf(s_gates[128 + t]);
            float og = sigm(s_gates[192 + t]);
            float cn = fg * c_in[b * 64 + t] + ig * gg;
            float hn = og * tanhf(cn);
            g_hn[b * 64 + t] = hn;
            out[OFF_HN + b * 64 + t] = hn;
            out[OFF_CN + b * 64 + t] = cn;
        }
    }
}

// ============================================================
// KB (consumer), 136 blocks x 256 thr, dsm 101120 B.
//  bid 0..127 : A tile (self-computes u, P, Q in-block)
//  bid 128..135: V per batch (raw two-matvec)
// ============================================================
__global__ void __launch_bounds__(256) k_cons(
        const float* __restrict__ ba2p,
        const float* __restrict__ Wv0, const float* __restrict__ bv0,
        const float* __restrict__ Wv1, const float* __restrict__ bv1,
        const float* __restrict__ Wv2, const float* __restrict__ bv2,
        float* __restrict__ out)
{
    extern __shared__ float sm[];
    const int bid = blockIdx.x;
    const int tid = threadIdx.x;

    if (bid >= 128) {
        // ---- V block ----
        __shared__ float shn2[64], sz0[128], sz1[128];
        const int b = bid - 128;
        if (tid < 64) shn2[tid] = g_hn[b * 64 + tid];
        __syncthreads();
        if (tid < 128) {
            float acc = bv0[tid];
            const float4* row = (const float4*)(Wv0 + tid * 64);
            #pragma unroll
            for (int j = 0; j < 16; j++) {
                float4 w4 = row[j];
                float4 x4 = *(const float4*)(shn2 + 4 * j);
                acc += w4.x * x4.x + w4.y * x4.y + w4.z * x4.z + w4.w * x4.w;
            }
            sz0[tid] = acc;  // no activation on layer 0
        }
        __syncthreads();
        if (tid < 128) {
            float acc = bv1[tid];
            const float4* row = (const float4*)(Wv1 + tid * 128);
            #pragma unroll 8
            for (int j = 0; j < 32; j++) {
                float4 w4 = row[j];
                float4 x4 = *(const float4*)(sz0 + 4 * j);
                acc += w4.x * x4.x + w4.y * x4.y + w4.z * x4.z + w4.w * x4.w;
            }
            sz1[tid] = (acc >= 0.f) ? acc : 0.01f * acc;
        }
        __syncthreads();
        if (tid < 32) {
            float4 x = *(const float4*)(sz1 + tid * 4);
            float4 ww = *(const float4*)(Wv2 + tid * 4);
            float s = ww.x * x.x + ww.y * x.y + ww.z * x.z + ww.w * x.w;
            s = warp_sum(s);
            if (tid == 0) out[OFF_V + b] = s + bv2[0];
        }
        return;
    }

    // ---- A tile block ----
    float* sVd = sm;            // 16384
    float* sW  = sm + 16384;    // 8192
    float* sC2 = sm + 24576;    // 256
    float* sC1 = sm + 24832;    // 128
    float* sP  = sm + 24960;    // 64
    float* sQ  = sm + 25024;    // 64
    float* sU  = sm + 25088;    // 128
    float* shn = sm + 25216;    // 64    (total 25280 floats)
    const int b = bid >> 4, oc = (bid >> 2) & 3, ic = bid & 3;

    const float* wsrc = g_wT  + b * 32768 + ic * 64;
    const float* vsrc = g_vvT + b * 32768 + oc * 64;

    // Phase A: stage sW, constants, hn
    #pragma unroll
    for (int l = tid; l < 2048; l += 256) {
        int gg = l >> 4, q = (l & 15) << 2;
        float4 wv = *(const float4*)(wsrc + gg * 256 + q);
        *(float4*)(sW + gg * 64 + q) = wv;
    }
    sC2[tid] = g_c2d[tid & 255];
    if (tid < 128) sC1[tid] = g_c1[tid];
    if (tid < 64)  shn[tid] = g_hn[b * 64 + tid];
    __syncthreads();

    // Phase B: u = bba + M2 . hn
    if (tid < 128) {
        float acc = g_bba[tid];
        const float4* row = (const float4*)(g_M2 + tid * 64);
        #pragma unroll
        for (int j = 0; j < 16; j++) {
            float4 w4 = row[j];
            float4 x4 = *(const float4*)(shn + 4 * j);
            acc += w4.x * x4.x + w4.y * x4.y + w4.z * x4.z + w4.w * x4.w;
        }
        sU[tid] = acc;
    }
    __syncthreads();

    // Phase C: build sVd = (vv + u) duplicated pairs
    #pragma unroll
    for (int l = tid; l < 2048; l += 256) {
        int gg = l >> 4, q = (l & 15) << 2;
        float uu = sU[gg];
        float4 vv = *(const float4*)(vsrc + gg * 256 + q);
        vv.x += uu; vv.y += uu; vv.z += uu; vv.w += uu;
        float* vd = sVd + gg * 128 + q * 2;
        ((float4*)vd)[0] = make_float4(vv.x, vv.x, vv.y, vv.y);
        ((float4*)vd)[1] = make_float4(vv.z, vv.z, vv.w, vv.w);
    }
    __syncthreads();

    // Phase D: P (incl. u-part) and Q from staged tiles
    if (tid < 64) {
        float s0 = 0.f, s1 = 0.f;
        #pragma unroll 4
        for (int g = 0; g < 128; g += 2) {
            s0 += sC1[g]     * sVd[g * 128 + 2 * tid];
            s1 += sC1[g + 1] * sVd[(g + 1) * 128 + 2 * tid];
        }
        sP[tid] = s0 + s1;
    } else if (tid < 128) {
        int i = tid - 64;
        float s0 = 0.f, s1 = 0.f;
        #pragma unroll 4
        for (int g = 0; g < 128; g += 2) {
            s0 += sC1[g]     * sW[g * 64 + i];
            s1 += sC1[g + 1] * sW[(g + 1) * 64 + i];
        }
        sQ[i] = s0 + s1;
    }
    __syncthreads();

    // Phase E: main f32x2 loop
    const int tx = tid & 15, ty = tid >> 4;
    unsigned long long a00 = 0, a01 = 0, a10 = 0, a11 = 0,
                       a20 = 0, a21 = 0, a30 = 0, a31 = 0;
    const float* vbase = sVd + ty * 8;
    const float* wbase = sW + tx * 4;
    const unsigned long long* c2base = (const unsigned long long*)sC2;
    const unsigned long long MASK = 0x7FFFFFFF7FFFFFFFULL;

    #pragma unroll 4
    for (int gg = 0; gg < 128; gg++) {
        ulonglong2 vp01 = *(const ulonglong2*)(vbase + gg * 128);
        ulonglong2 vp23 = *(const ulonglong2*)(vbase + gg * 128 + 4);
        ulonglong2 wp   = *(const ulonglong2*)(wbase + gg * 64);
        unsigned long long c2 = c2base[gg];
        unsigned long long tt;
        tt = addp(vp01.x, wp.x) & MASK;  a00 = fmap(c2, tt, a00);
        tt = addp(vp01.x, wp.y) & MASK;  a01 = fmap(c2, tt, a01);
        tt = addp(vp01.y, wp.x) & MASK;  a10 = fmap(c2, tt, a10);
        tt = addp(vp01.y, wp.y) & MASK;  a11 = fmap(c2, tt, a11);
        tt = addp(vp23.x, wp.x) & MASK;  a20 = fmap(c2, tt, a20);
        tt = addp(vp23.x, wp.y) & MASK;  a21 = fmap(c2, tt, a21);
        tt = addp(vp23.y, wp.x) & MASK;  a30 = fmap(c2, tt, a30);
        tt = addp(vp23.y, wp.y) & MASK;  a31 = fmap(c2, tt, a31);
    }

    const float ba2v = ba2p[0];
    float4 q4 = *(const float4*)(sQ + tx * 4);
    unsigned long long acc[4][2] = {{a00,a01},{a10,a11},{a20,a21},{a30,a31}};
    #pragma unroll
    for (int r = 0; r < 4; r++) {
        float pr = sP[ty * 4 + r] + ba2v;
        float4 res;
        res.x = __uint_as_float((unsigned)(acc[r][0] & 0xffffffffULL)) + pr + q4.x;
        res.y = __uint_as_float((unsigned)(acc[r][0] >> 32))           + pr + q4.y;
        res.z = __uint_as_float((unsigned)(acc[r][1] & 0xffffffffULL)) + pr + q4.z;
        res.w = __uint_as_float((unsigned)(acc[r][1] >> 32))           + pr + q4.w;
        int og = oc * 64 + ty * 4 + r;
        *(float4*)(out + OFF_A + b * 65536 + og * 256 + ic * 64 + tx * 4) = res;
    }
}

// ============================================================
extern "C" void kernel_launch(void* const* d_in, const int* in_sizes, int n_in,
                              void* d_out, int out_size)
{
    const float* ope   = (const float*)d_in[0];
    const float* ins   = (const float*)d_in[1];
    const float* h_in  = (const float*)d_in[2];
    const float* c_in  = (const float*)d_in[3];
    const float* W_ih  = (const float*)d_in[4];
    const float* W_hh  = (const float*)d_in[5];
    const float* b_ih  = (const float*)d_in[6];
    const float* b_hh  = (const float*)d_in[7];
    const float* Wv0   = (const float*)d_in[8];
    const float* bv0   = (const float*)d_in[9];
    const float* Wv1   = (const float*)d_in[10];
    const float* bv1   = (const float*)d_in[11];
    const float* Wv2   = (const float*)d_in[12];
    const float* bv2   = (const float*)d_in[13];
    const float* Wa0   = (const float*)d_in[14];
    const float* ba0   = (const float*)d_in[15];
    const float* Wa1   = (const float*)d_in[16];
    const float* ba1   = (const float*)d_in[17];
    const float* Wa2   = (const float*)d_in[18];
    const float* ba2   = (const float*)d_in[19];
    float* out = (float*)d_out;

    cudaFuncSetAttribute(k_prod, cudaFuncAttributeMaxDynamicSharedMemorySize, 49472);
    cudaFuncSetAttribute(k_cons, cudaFuncAttributeMaxDynamicSharedMemorySize, 101120);

    k_prod<<<145, 256, 49472>>>(ope, ins, h_in, c_in, W_ih, W_hh, b_ih, b_hh,
                                Wa0, ba0, Wa1, ba1, Wa2, out);
    k_cons<<<136, 256, 101120>>>(ba2, Wv0, bv0, Wv1, bv1, Wv2, bv2, out);
}

// round 14
// speedup vs baseline: 1.2320x; 1.0950x over previous
#include <cuda_runtime.h>
#include <math.h>

// B=8, D=64, O=256, I=256, G=128
// Output: V(8) | A(8*65536) | hn(8*64) | cn(8*64)
#define OFF_V  0
#define OFF_A  8
#define OFF_HN 524296
#define OFF_CN 524808

// ---- scratch ----
__device__ float g_hn[8 * 64];
__device__ float g_M2[128 * 64];        // Wa1@Ws
__device__ float g_bba[128];            // Wa1@ba0 + ba1
__device__ float g_c1[128];
__device__ float g_c2d[256];
__device__ float g_vvT[8 * 128 * 256];  // [b][g][o]  (raw, no u)
__device__ float g_wT[8 * 128 * 256];   // [b][g][i]

__device__ __forceinline__ float sigm(float x) { return 1.0f / (1.0f + expf(-x)); }

__device__ __forceinline__ float warp_sum(float v) {
    #pragma unroll
    for (int o = 16; o; o >>= 1) v += __shfl_xor_sync(0xffffffffu, v, o);
    return v;
}

__device__ __forceinline__ unsigned long long addp(unsigned long long a, unsigned long long b) {
    unsigned long long r;
    asm("add.rn.f32x2 %0, %1, %2;" : "=l"(r) : "l"(a), "l"(b));
    return r;
}
__device__ __forceinline__ unsigned long long fmap(unsigned long long a, unsigned long long b, unsigned long long c) {
    unsigned long long r;
    asm("fma.rn.f32x2 %0, %1, %2, %3;" : "=l"(r) : "l"(a), "l"(b), "l"(c));
    return r;
}
__device__ __forceinline__ float plo(unsigned long long p) {
    return __uint_as_float((unsigned)(p & 0xffffffffULL));
}
__device__ __forceinline__ float phi(unsigned long long p) {
    return __uint_as_float((unsigned)(p >> 32));
}

// ============================================================
// KA (producer), 145 blocks x 256 thr, dsm 69888 B.
//  bid 0..127 : vv/w block (m = bid>>6, b = (bid>>3)&7, gc = bid&7):
//               in-block M-chunk GEMM, then 16 g-rows x 256 x (packed f32x2)
//  bid 128..135: LSTM per batch.
//  bid 136..143: M2 chunk gc.
//  bid 144     : bias (bba, c1, c2d).
// ============================================================
__global__ void __launch_bounds__(256) k_prod(
        const float* __restrict__ ope,  const float* __restrict__ ins,
        const float* __restrict__ h_in, const float* __restrict__ c_in,
        const float* __restrict__ W_ih, const float* __restrict__ W_hh,
        const float* __restrict__ b_ih, const float* __restrict__ b_hh,
        const float* __restrict__ Wa0,  const float* __restrict__ ba0,
        const float* __restrict__ Wa1,  const float* __restrict__ ba1,
        const float* __restrict__ Wa2,
        float* __restrict__ out)
{
    extern __shared__ float dsm[];
    const int bid = blockIdx.x;
    const int t = threadIdx.x;

    if (bid < 128 || (bid >= 136 && bid < 144)) {
        // ---- GEMM-based block ----
        const bool isM2 = (bid >= 136);
        const int m  = isM2 ? 2 : (bid >> 6);
        const int b  = isM2 ? 0 : ((bid >> 3) & 7);
        const int gc = isM2 ? (bid - 136) : (bid & 7);

        float* sA = dsm;              // 16*129 = 2064
        float* sB = dsm + 2064;       // 128*72 = 9216 (ends 11280)
        float* sM = dsm + 16384;      // 16*68  = 1088 (ends 17472)
        float* sIn = dsm;             // [0..16384) both chunks, after GEMM

        // stage A: Wa1 rows [gc*16, +16)
        #pragma unroll
        for (int i = 0; i < 8; i++) {
            int idx = t + i * 256;
            sA[(idx >> 7) * 129 + (idx & 127)] = Wa1[gc * 2048 + idx];
        }
        // stage B: Wa0 column slice (m0: +64, m1: +128, m2: +0)
        const int coff = (m == 2) ? 0 : (64 + m * 64);
        {
            int hh0 = t >> 4, c4 = t & 15;
            #pragma unroll
            for (int i = 0; i < 8; i++) {
                int hh = hh0 + i * 16;
                float4 v = *(const float4*)(Wa0 + hh * 192 + coff + c4 * 4);
                *(float4*)(sB + hh * 72 + c4 * 4) = v;
            }
        }
        __syncthreads();

        // M-chunk GEMM: 16 x 64, K=128
        {
            const int g = t >> 4, dg = t & 15;
            float4 acc = make_float4(0.f, 0.f, 0.f, 0.f);
            const float* ar = sA + g * 129;
            const float* bc = sB + dg * 4;
            #pragma unroll 8
            for (int hh = 0; hh < 128; hh++) {
                float a = ar[hh];
                float4 bv = *(const float4*)(bc + hh * 72);
                acc.x += a * bv.x; acc.y += a * bv.y; acc.z += a * bv.z; acc.w += a * bv.w;
            }
            *(float4*)(sM + g * 68 + dg * 4) = acc;
        }
        __syncthreads();

        if (isM2) {
            const int g = t >> 4, dg = t & 15;
            *(float4*)(g_M2 + (gc * 16 + g) * 64 + dg * 4) =
                *(const float4*)(sM + g * 68 + dg * 4);
            return;
        }

        // load this thread's M row as packed pairs
        const int g = t & 15, xg = t >> 4;
        unsigned long long mu[32];
        #pragma unroll
        for (int j = 0; j < 16; j++) {
            ulonglong2 p = *(const ulonglong2*)(sM + g * 68 + 4 * j);
            mu[2 * j] = p.x; mu[2 * j + 1] = p.y;
        }

        // stage BOTH input chunks (16384 floats) in one burst
        const float* src = (m == 0) ? (ope + (b * 258 + 1) * 64)
                                    : (ins + b * 256 * 64);
        {
            const float4* g4 = (const float4*)src;
            #pragma unroll
            for (int k = 0; k < 16; k++)
                ((float4*)sIn)[t + k * 256] = g4[t + k * 256];
        }
        __syncthreads();

        // 16 rows per thread (8 per chunk), packed f32x2 dots
        float accs[16];
        #pragma unroll 4
        for (int rr = 0; rr < 16; rr++) {
            int row = (rr >> 3) * 128 + xg * 8 + (rr & 7);
            const ulonglong2* ip = (const ulonglong2*)(sIn + row * 64);
            unsigned long long a0 = 0ULL, a1 = 0ULL;
            #pragma unroll
            for (int j = 0; j < 16; j++) {
                ulonglong2 xx = ip[j];
                a0 = fmap(mu[2 * j], xx.x, a0);
                a1 = fmap(mu[2 * j + 1], xx.y, a1);
            }
            accs[rr] = plo(a0) + phi(a0) + plo(a1) + phi(a1);
        }

        float* dst = ((m == 0) ? g_vvT : g_wT) + b * 32768 + (gc * 16 + g) * 256 + xg * 8;
        *(float4*)(dst)           = make_float4(accs[0],  accs[1],  accs[2],  accs[3]);
        *(float4*)(dst + 4)       = make_float4(accs[4],  accs[5],  accs[6],  accs[7]);
        *(float4*)(dst + 128)     = make_float4(accs[8],  accs[9],  accs[10], accs[11]);
        *(float4*)(dst + 132)     = make_float4(accs[12], accs[13], accs[14], accs[15]);
        return;
    }

    if (bid == 144) {
        // ---- bias block: bba, c1, c2d ----
        __shared__ float sb[128];
        if (t < 128) sb[t] = ba0[t];
        __syncthreads();
        if (t < 128) {
            float acc = ba1[t];
            const float4* row = (const float4*)(Wa1 + t * 128);
            #pragma unroll 8
            for (int j = 0; j < 32; j++) {
                float4 w4 = row[j];
                float4 x4 = *(const float4*)(sb + j * 4);
                acc += w4.x * x4.x + w4.y * x4.y + w4.z * x4.z + w4.w * x4.w;
            }
            g_bba[t] = acc;
            float w2 = Wa2[t];
            g_c1[t] = 0.505f * w2;
            g_c2d[2 * t]     = 0.495f * w2;
            g_c2d[2 * t + 1] = 0.495f * w2;
        }
        return;
    }

    // ---- LSTM block (bid 128..135) ----
    {
        __shared__ float sPart[1024];
        __shared__ float s_x[128];
        __shared__ float s_gates[256];
        const int b = bid - 128;

        float4 wi[16];
        {
            const float4* pwi = (const float4*)(W_ih + t * 64);
            #pragma unroll
            for (int j = 0; j < 16; j++) wi[j] = pwi[j];
        }
        {
            int dq = t & 15, rc = t >> 4;
            const float* base = ope + (b * 258 + 1 + rc * 16) * 64 + dq * 4;
            float4 s = make_float4(0.f, 0.f, 0.f, 0.f);
            #pragma unroll
            for (int rr = 0; rr < 16; rr++) {
                float4 x = *(const float4*)(base + rr * 64);
                s.x += x.x; s.y += x.y; s.z += x.z; s.w += x.w;
            }
            *(float4*)(sPart + rc * 64 + dq * 4) = s;
        }
        if (t >= 64 && t < 128) s_x[t] = h_in[b * 64 + (t - 64)];
        __syncthreads();
        if (t < 64) {
            float s = 0.f;
            #pragma unroll
            for (int rc = 0; rc < 16; rc++) s += sPart[rc * 64 + t];
            s_x[t] = s * (1.0f / 256.0f);
        }
        __syncthreads();

        float acc = b_ih[t] + b_hh[t];
        #pragma unroll
        for (int j = 0; j < 16; j++) {
            float4 x4 = *(const float4*)(s_x + j * 4);
            acc += wi[j].x * x4.x + wi[j].y * x4.y + wi[j].z * x4.z + wi[j].w * x4.w;
        }
        {
            float4 wh[16];
            const float4* pwh = (const float4*)(W_hh + t * 64);
            #pragma unroll
            for (int j = 0; j < 16; j++) wh[j] = pwh[j];
            #pragma unroll
            for (int j = 0; j < 16; j++) {
                float4 x4 = *(const float4*)(s_x + 64 + j * 4);
                acc += wh[j].x * x4.x + wh[j].y * x4.y + wh[j].z * x4.z + wh[j].w * x4.w;
            }
        }
        s_gates[t] = acc;
        __syncthreads();

        if (t < 64) {
            float ig = sigm(s_gates[t]);
            float fg = sigm(s_gates[64 + t]);
            float gg = tanhf(s_gates[128 + t]);
            float og = sigm(s_gates[192 + t]);
            float cn = fg * c_in[b * 64 + t] + ig * gg;
            float hn = og * tanhf(cn);
            g_hn[b * 64 + t] = hn;
            out[OFF_HN + b * 64 + t] = hn;
            out[OFF_CN + b * 64 + t] = cn;
        }
    }
}

// ============================================================
// KB (consumer), 136 blocks x 256 thr, dsm 101120 B.
//  bid 0..127 : A tile (vv prefetched to regs; u/Q in Phase B; P in D)
//  bid 128..135: V per batch (raw two-matvec)
// ============================================================
__global__ void __launch_bounds__(256) k_cons(
        const float* __restrict__ ba2p,
        const float* __restrict__ Wv0, const float* __restrict__ bv0,
        const float* __restrict__ Wv1, const float* __restrict__ bv1,
        const float* __restrict__ Wv2, const float* __restrict__ bv2,
        float* __restrict__ out)
{
    extern __shared__ float sm[];
    const int bid = blockIdx.x;
    const int tid = threadIdx.x;

    if (bid >= 128) {
        // ---- V block ----
        __shared__ float shn2[64], sz0[128], sz1[128];
        const int b = bid - 128;
        if (tid < 64) shn2[tid] = g_hn[b * 64 + tid];
        __syncthreads();
        if (tid < 128) {
            float acc = bv0[tid];
            const float4* row = (const float4*)(Wv0 + tid * 64);
            #pragma unroll
            for (int j = 0; j < 16; j++) {
                float4 w4 = row[j];
                float4 x4 = *(const float4*)(shn2 + 4 * j);
                acc += w4.x * x4.x + w4.y * x4.y + w4.z * x4.z + w4.w * x4.w;
            }
            sz0[tid] = acc;  // no activation on layer 0
        }
        __syncthreads();
        if (tid < 128) {
            float acc = bv1[tid];
            const float4* row = (const float4*)(Wv1 + tid * 128);
            #pragma unroll 8
            for (int j = 0; j < 32; j++) {
                float4 w4 = row[j];
                float4 x4 = *(const float4*)(sz0 + 4 * j);
                acc += w4.x * x4.x + w4.y * x4.y + w4.z * x4.z + w4.w * x4.w;
            }
            sz1[tid] = (acc >= 0.f) ? acc : 0.01f * acc;
        }
        __syncthreads();
        if (tid < 32) {
            float4 x = *(const float4*)(sz1 + tid * 4);
            float4 ww = *(const float4*)(Wv2 + tid * 4);
            float s = ww.x * x.x + ww.y * x.y + ww.z * x.z + ww.w * x.w;
            s = warp_sum(s);
            if (tid == 0) out[OFF_V + b] = s + bv2[0];
        }
        return;
    }

    // ---- A tile block ----
    float* sVd = sm;            // 16384
    float* sW  = sm + 16384;    // 8192
    float* sC2 = sm + 24576;    // 256
    float* sC1 = sm + 24832;    // 128
    float* sP  = sm + 24960;    // 64
    float* sQ  = sm + 25024;    // 64
    float* sU  = sm + 25088;    // 128
    float* shn = sm + 25216;    // 64    (total 25280 floats)
    const int b = bid >> 4, oc = (bid >> 2) & 3, ic = bid & 3;

    const float* wsrc = g_wT  + b * 32768 + ic * 64;
    const float* vsrc = g_vvT + b * 32768 + oc * 64;

    // Phase A: prefetch vv tile to registers (same (gg,q) mapping as Phase C);
    //          stage sW, constants, hn
    float4 vreg[8];
    #pragma unroll
    for (int k = 0; k < 8; k++) {
        int l = tid + k * 256;
        int gg = l >> 4, q = (l & 15) << 2;
        vreg[k] = *(const float4*)(vsrc + gg * 256 + q);
    }
    #pragma unroll
    for (int l = tid; l < 2048; l += 256) {
        int gg = l >> 4, q = (l & 15) << 2;
        float4 wv = *(const float4*)(wsrc + gg * 256 + q);
        *(float4*)(sW + gg * 64 + q) = wv;
    }
    sC2[tid] = g_c2d[tid & 255];
    if (tid < 128) sC1[tid] = g_c1[tid];
    if (tid < 64)  shn[tid] = g_hn[b * 64 + tid];
    __syncthreads();

    // Phase B: u (tid<128) ; Q (tid 128..191)
    if (tid < 128) {
        float acc = g_bba[tid];
        const float4* row = (const float4*)(g_M2 + tid * 64);
        #pragma unroll
        for (int j = 0; j < 16; j++) {
            float4 w4 = row[j];
            float4 x4 = *(const float4*)(shn + 4 * j);
            acc += w4.x * x4.x + w4.y * x4.y + w4.z * x4.z + w4.w * x4.w;
        }
        sU[tid] = acc;
    } else if (tid < 192) {
        int i = tid - 128;
        float s0 = 0.f, s1 = 0.f;
        #pragma unroll 4
        for (int g = 0; g < 128; g += 2) {
            s0 += sC1[g]     * sW[g * 64 + i];
            s1 += sC1[g + 1] * sW[(g + 1) * 64 + i];
        }
        sQ[i] = s0 + s1;
    }
    __syncthreads();

    // Phase C: build sVd = (vv + u) duplicated pairs, from registers
    #pragma unroll
    for (int k = 0; k < 8; k++) {
        int l = tid + k * 256;
        int gg = l >> 4, q = (l & 15) << 2;
        float uu = sU[gg];
        float4 vv = vreg[k];
        vv.x += uu; vv.y += uu; vv.z += uu; vv.w += uu;
        float* vd = sVd + gg * 128 + q * 2;
        ((float4*)vd)[0] = make_float4(vv.x, vv.x, vv.y, vv.y);
        ((float4*)vd)[1] = make_float4(vv.z, vv.z, vv.w, vv.w);
    }
    __syncthreads();

    // Phase D: P (incl. u-part via sVd)
    if (tid < 64) {
        float s0 = 0.f, s1 = 0.f;
        #pragma unroll 4
        for (int g = 0; g < 128; g += 2) {
            s0 += sC1[g]     * sVd[g * 128 + 2 * tid];
            s1 += sC1[g + 1] * sVd[(g + 1) * 128 + 2 * tid];
        }
        sP[tid] = s0 + s1;
    }
    __syncthreads();

    // Phase E: main f32x2 loop
    const int tx = tid & 15, ty = tid >> 4;
    unsigned long long a00 = 0, a01 = 0, a10 = 0, a11 = 0,
                       a20 = 0, a21 = 0, a30 = 0, a31 = 0;
    const float* vbase = sVd + ty * 8;
    const float* wbase = sW + tx * 4;
    const unsigned long long* c2base = (const unsigned long long*)sC2;
    const unsigned long long MASK = 0x7FFFFFFF7FFFFFFFULL;

    #pragma unroll 4
    for (int gg = 0; gg < 128; gg++) {
        ulonglong2 vp01 = *(const ulonglong2*)(vbase + gg * 128);
        ulonglong2 vp23 = *(const ulonglong2*)(vbase + gg * 128 + 4);
        ulonglong2 wp   = *(const ulonglong2*)(wbase + gg * 64);
        unsigned long long c2 = c2base[gg];
        unsigned long long tt;
        tt = addp(vp01.x, wp.x) & MASK;  a00 = fmap(c2, tt, a00);
        tt = addp(vp01.x, wp.y) & MASK;  a01 = fmap(c2, tt, a01);
        tt = addp(vp01.y, wp.x) & MASK;  a10 = fmap(c2, tt, a10);
        tt = addp(vp01.y, wp.y) & MASK;  a11 = fmap(c2, tt, a11);
        tt = addp(vp23.x, wp.x) & MASK;  a20 = fmap(c2, tt, a20);
        tt = addp(vp23.x, wp.y) & MASK;  a21 = fmap(c2, tt, a21);
        tt = addp(vp23.y, wp.x) & MASK;  a30 = fmap(c2, tt, a30);
        tt = addp(vp23.y, wp.y) & MASK;  a31 = fmap(c2, tt, a31);
    }

    const float ba2v = ba2p[0];
    float4 q4 = *(const float4*)(sQ + tx * 4);
    unsigned long long acc[4][2] = {{a00,a01},{a10,a11},{a20,a21},{a30,a31}};
    #pragma unroll
    for (int r = 0; r < 4; r++) {
        float pr = sP[ty * 4 + r] + ba2v;
        float4 res;
        res.x = plo(acc[r][0]) + pr + q4.x;
        res.y = phi(acc[r][0]) + pr + q4.y;
        res.z = plo(acc[r][1]) + pr + q4.z;
        res.w = phi(acc[r][1]) + pr + q4.w;
        int og = oc * 64 + ty * 4 + r;
        *(float4*)(out + OFF_A + b * 65536 + og * 256 + ic * 64 + tx * 4) = res;
    }
}

// ============================================================
extern "C" void kernel_launch(void* const* d_in, const int* in_sizes, int n_in,
                              void* d_out, int out_size)
{
    const float* ope   = (const float*)d_in[0];
    const float* ins   = (const float*)d_in[1];
    const float* h_in  = (const float*)d_in[2];
    const float* c_in  = (const float*)d_in[3];
    const float* W_ih  = (const float*)d_in[4];
    const float* W_hh  = (const float*)d_in[5];
    const float* b_ih  = (const float*)d_in[6];
    const float* b_hh  = (const float*)d_in[7];
    const float* Wv0   = (const float*)d_in[8];
    const float* bv0   = (const float*)d_in[9];
    const float* Wv1   = (const float*)d_in[10];
    const float* bv1   = (const float*)d_in[11];
    const float* Wv2   = (const float*)d_in[12];
    const float* bv2   = (const float*)d_in[13];
    const float* Wa0   = (const float*)d_in[14];
    const float* ba0   = (const float*)d_in[15];
    const float* Wa1   = (const float*)d_in[16];
    const float* ba1   = (const float*)d_in[17];
    const float* Wa2   = (const float*)d_in[18];
    const float* ba2   = (const float*)d_in[19];
    float* out = (float*)d_out;

    cudaFuncSetAttribute(k_prod, cudaFuncAttributeMaxDynamicSharedMemorySize, 69888);
    cudaFuncSetAttribute(k_cons, cudaFuncAttributeMaxDynamicSharedMemorySize, 101120);

    k_prod<<<145, 256, 69888>>>(ope, ins, h_in, c_in, W_ih, W_hh, b_ih, b_hh,
                                Wa0, ba0, Wa1, ba1, Wa2, out);
    k_cons<<<136, 256, 101120>>>(ba2, Wv0, bv0, Wv1, bv1, Wv2, bv2, out);
}

// round 15
// speedup vs baseline: 1.3091x; 1.0626x over previous
#include <cuda_runtime.h>
#include <math.h>

// B=8, D=64, O=256, I=256, G=128
// Output: V(8) | A(8*65536) | hn(8*64) | cn(8*64)
#define OFF_V  0
#define OFF_A  8
#define OFF_HN 524296
#define OFF_CN 524808

// ---- scratch ----
__device__ float g_hn[8 * 64];
__device__ float g_M2[128 * 64];        // Wa1@Ws
__device__ float g_bba[128];            // Wa1@ba0 + ba1
__device__ float g_c1[128];
__device__ float g_c2d[256];
__device__ float g_vvT[8 * 128 * 256];  // [b][g][o]  (raw, no u)
__device__ float g_wT[8 * 128 * 256];   // [b][g][i]

__device__ __forceinline__ float sigm(float x) { return 1.0f / (1.0f + expf(-x)); }

__device__ __forceinline__ float warp_sum(float v) {
    #pragma unroll
    for (int o = 16; o; o >>= 1) v += __shfl_xor_sync(0xffffffffu, v, o);
    return v;
}

__device__ __forceinline__ unsigned long long addp(unsigned long long a, unsigned long long b) {
    unsigned long long r;
    asm("add.rn.f32x2 %0, %1, %2;" : "=l"(r) : "l"(a), "l"(b));
    return r;
}
__device__ __forceinline__ unsigned long long fmap(unsigned long long a, unsigned long long b, unsigned long long c) {
    unsigned long long r;
    asm("fma.rn.f32x2 %0, %1, %2, %3;" : "=l"(r) : "l"(a), "l"(b), "l"(c));
    return r;
}
__device__ __forceinline__ float plo(unsigned long long p) {
    return __uint_as_float((unsigned)(p & 0xffffffffULL));
}
__device__ __forceinline__ float phi(unsigned long long p) {
    return __uint_as_float((unsigned)(p >> 32));
}

// ============================================================
// KA (producer), 145 blocks x 256 thr, dsm 69888 B. (unchanged)
//  bid 0..127 : vv/w block (m = bid>>6, b = (bid>>3)&7, gc = bid&7)
//  bid 128..135: LSTM per batch.
//  bid 136..143: M2 chunk gc.
//  bid 144     : bias (bba, c1, c2d).
// ============================================================
__global__ void __launch_bounds__(256) k_prod(
        const float* __restrict__ ope,  const float* __restrict__ ins,
        const float* __restrict__ h_in, const float* __restrict__ c_in,
        const float* __restrict__ W_ih, const float* __restrict__ W_hh,
        const float* __restrict__ b_ih, const float* __restrict__ b_hh,
        const float* __restrict__ Wa0,  const float* __restrict__ ba0,
        const float* __restrict__ Wa1,  const float* __restrict__ ba1,
        const float* __restrict__ Wa2,
        float* __restrict__ out)
{
    extern __shared__ float dsm[];
    const int bid = blockIdx.x;
    const int t = threadIdx.x;

    if (bid < 128 || (bid >= 136 && bid < 144)) {
        const bool isM2 = (bid >= 136);
        const int m  = isM2 ? 2 : (bid >> 6);
        const int b  = isM2 ? 0 : ((bid >> 3) & 7);
        const int gc = isM2 ? (bid - 136) : (bid & 7);

        float* sA = dsm;              // 16*129
        float* sB = dsm + 2064;       // 128*72
        float* sM = dsm + 16384;      // 16*68
        float* sIn = dsm;             // [0..16384) after GEMM

        #pragma unroll
        for (int i = 0; i < 8; i++) {
            int idx = t + i * 256;
            sA[(idx >> 7) * 129 + (idx & 127)] = Wa1[gc * 2048 + idx];
        }
        const int coff = (m == 2) ? 0 : (64 + m * 64);
        {
            int hh0 = t >> 4, c4 = t & 15;
            #pragma unroll
            for (int i = 0; i < 8; i++) {
                int hh = hh0 + i * 16;
                float4 v = *(const float4*)(Wa0 + hh * 192 + coff + c4 * 4);
                *(float4*)(sB + hh * 72 + c4 * 4) = v;
            }
        }
        __syncthreads();

        {
            const int g = t >> 4, dg = t & 15;
            float4 acc = make_float4(0.f, 0.f, 0.f, 0.f);
            const float* ar = sA + g * 129;
            const float* bc = sB + dg * 4;
            #pragma unroll 8
            for (int hh = 0; hh < 128; hh++) {
                float a = ar[hh];
                float4 bv = *(const float4*)(bc + hh * 72);
                acc.x += a * bv.x; acc.y += a * bv.y; acc.z += a * bv.z; acc.w += a * bv.w;
            }
            *(float4*)(sM + g * 68 + dg * 4) = acc;
        }
        __syncthreads();

        if (isM2) {
            const int g = t >> 4, dg = t & 15;
            *(float4*)(g_M2 + (gc * 16 + g) * 64 + dg * 4) =
                *(const float4*)(sM + g * 68 + dg * 4);
            return;
        }

        const int g = t & 15, xg = t >> 4;
        unsigned long long mu[32];
        #pragma unroll
        for (int j = 0; j < 16; j++) {
            ulonglong2 p = *(const ulonglong2*)(sM + g * 68 + 4 * j);
            mu[2 * j] = p.x; mu[2 * j + 1] = p.y;
        }

        const float* src = (m == 0) ? (ope + (b * 258 + 1) * 64)
                                    : (ins + b * 256 * 64);
        {
            const float4* g4 = (const float4*)src;
            #pragma unroll
            for (int k = 0; k < 16; k++)
                ((float4*)sIn)[t + k * 256] = g4[t + k * 256];
        }
        __syncthreads();

        float accs[16];
        #pragma unroll 4
        for (int rr = 0; rr < 16; rr++) {
            int row = (rr >> 3) * 128 + xg * 8 + (rr & 7);
            const ulonglong2* ip = (const ulonglong2*)(sIn + row * 64);
            unsigned long long a0 = 0ULL, a1 = 0ULL;
            #pragma unroll
            for (int j = 0; j < 16; j++) {
                ulonglong2 xx = ip[j];
                a0 = fmap(mu[2 * j], xx.x, a0);
                a1 = fmap(mu[2 * j + 1], xx.y, a1);
            }
            accs[rr] = plo(a0) + phi(a0) + plo(a1) + phi(a1);
        }

        float* dst = ((m == 0) ? g_vvT : g_wT) + b * 32768 + (gc * 16 + g) * 256 + xg * 8;
        *(float4*)(dst)           = make_float4(accs[0],  accs[1],  accs[2],  accs[3]);
        *(float4*)(dst + 4)       = make_float4(accs[4],  accs[5],  accs[6],  accs[7]);
        *(float4*)(dst + 128)     = make_float4(accs[8],  accs[9],  accs[10], accs[11]);
        *(float4*)(dst + 132)     = make_float4(accs[12], accs[13], accs[14], accs[15]);
        return;
    }

    if (bid == 144) {
        __shared__ float sb[128];
        if (t < 128) sb[t] = ba0[t];
        __syncthreads();
        if (t < 128) {
            float acc = ba1[t];
            const float4* row = (const float4*)(Wa1 + t * 128);
            #pragma unroll 8
            for (int j = 0; j < 32; j++) {
                float4 w4 = row[j];
                float4 x4 = *(const float4*)(sb + j * 4);
                acc += w4.x * x4.x + w4.y * x4.y + w4.z * x4.z + w4.w * x4.w;
            }
            g_bba[t] = acc;
            float w2 = Wa2[t];
            g_c1[t] = 0.505f * w2;
            g_c2d[2 * t]     = 0.495f * w2;
            g_c2d[2 * t + 1] = 0.495f * w2;
        }
        return;
    }

    // ---- LSTM block (bid 128..135) ----
    {
        __shared__ float sPart[1024];
        __shared__ float s_x[128];
        __shared__ float s_gates[256];
        const int b = bid - 128;

        float4 wi[16];
        {
            const float4* pwi = (const float4*)(W_ih + t * 64);
            #pragma unroll
            for (int j = 0; j < 16; j++) wi[j] = pwi[j];
        }
        {
            int dq = t & 15, rc = t >> 4;
            const float* base = ope + (b * 258 + 1 + rc * 16) * 64 + dq * 4;
            float4 s = make_float4(0.f, 0.f, 0.f, 0.f);
            #pragma unroll
            for (int rr = 0; rr < 16; rr++) {
                float4 x = *(const float4*)(base + rr * 64);
                s.x += x.x; s.y += x.y; s.z += x.z; s.w += x.w;
            }
            *(float4*)(sPart + rc * 64 + dq * 4) = s;
        }
        if (t >= 64 && t < 128) s_x[t] = h_in[b * 64 + (t - 64)];
        __syncthreads();
        if (t < 64) {
            float s = 0.f;
            #pragma unroll
            for (int rc = 0; rc < 16; rc++) s += sPart[rc * 64 + t];
            s_x[t] = s * (1.0f / 256.0f);
        }
        __syncthreads();

        float acc = b_ih[t] + b_hh[t];
        #pragma unroll
        for (int j = 0; j < 16; j++) {
            float4 x4 = *(const float4*)(s_x + j * 4);
            acc += wi[j].x * x4.x + wi[j].y * x4.y + wi[j].z * x4.z + wi[j].w * x4.w;
        }
        {
            float4 wh[16];
            const float4* pwh = (const float4*)(W_hh + t * 64);
            #pragma unroll
            for (int j = 0; j < 16; j++) wh[j] = pwh[j];
            #pragma unroll
            for (int j = 0; j < 16; j++) {
                float4 x4 = *(const float4*)(s_x + 64 + j * 4);
                acc += wh[j].x * x4.x + wh[j].y * x4.y + wh[j].z * x4.z + wh[j].w * x4.w;
            }
        }
        s_gates[t] = acc;
        __syncthreads();

        if (t < 64) {
            float ig = sigm(s_gates[t]);
            float fg = sigm(s_gates[64 + t]);
            float gg = tanhf(s_gates[128 + t]);
            float og = sigm(s_gates[192 + t]);
            float cn = fg * c_in[b * 64 + t] + ig * gg;
            float hn = og * tanhf(cn);
            g_hn[b * 64 + t] = hn;
            out[OFF_HN + b * 64 + t] = hn;
            out[OFF_CN + b * 64 + t] = cn;
        }
    }
}

// ============================================================
// KB (consumer), 136 blocks x 512 thr, dsm 101120 B.
//  bid 0..127 : A tile, micro-tile 2o x 4i (16 warps/block)
//  bid 128..135: V per batch
// ============================================================
__global__ void __launch_bounds__(512) k_cons(
        const float* __restrict__ ba2p,
        const float* __restrict__ Wv0, const float* __restrict__ bv0,
        const float* __restrict__ Wv1, const float* __restrict__ bv1,
        const float* __restrict__ Wv2, const float* __restrict__ bv2,
        float* __restrict__ out)
{
    extern __shared__ float sm[];
    const int bid = blockIdx.x;
    const int tid = threadIdx.x;

    if (bid >= 128) {
        // ---- V block ----
        __shared__ float shn2[64], sz0[128], sz1[128];
        const int b = bid - 128;
        if (tid < 64) shn2[tid] = g_hn[b * 64 + tid];
        __syncthreads();
        if (tid < 128) {
            float acc = bv0[tid];
            const float4* row = (const float4*)(Wv0 + tid * 64);
            #pragma unroll
            for (int j = 0; j < 16; j++) {
                float4 w4 = row[j];
                float4 x4 = *(const float4*)(shn2 + 4 * j);
                acc += w4.x * x4.x + w4.y * x4.y + w4.z * x4.z + w4.w * x4.w;
            }
            sz0[tid] = acc;  // no activation on layer 0
        }
        __syncthreads();
        if (tid < 128) {
            float acc = bv1[tid];
            const float4* row = (const float4*)(Wv1 + tid * 128);
            #pragma unroll 8
            for (int j = 0; j < 32; j++) {
                float4 w4 = row[j];
                float4 x4 = *(const float4*)(sz0 + 4 * j);
                acc += w4.x * x4.x + w4.y * x4.y + w4.z * x4.z + w4.w * x4.w;
            }
            sz1[tid] = (acc >= 0.f) ? acc : 0.01f * acc;
        }
        __syncthreads();
        if (tid < 32) {
            float4 x = *(const float4*)(sz1 + tid * 4);
            float4 ww = *(const float4*)(Wv2 + tid * 4);
            float s = ww.x * x.x + ww.y * x.y + ww.z * x.z + ww.w * x.w;
            s = warp_sum(s);
            if (tid == 0) out[OFF_V + b] = s + bv2[0];
        }
        return;
    }

    // ---- A tile block (512 threads) ----
    float* sVd = sm;            // 16384
    float* sW  = sm + 16384;    // 8192
    float* sC2 = sm + 24576;    // 256
    float* sC1 = sm + 24832;    // 128
    float* sP  = sm + 24960;    // 64
    float* sQ  = sm + 25024;    // 64
    float* sU  = sm + 25088;    // 128
    float* shn = sm + 25216;    // 64
    const int b = bid >> 4, oc = (bid >> 2) & 3, ic = bid & 3;

    const float* wsrc = g_wT  + b * 32768 + ic * 64;
    const float* vsrc = g_vvT + b * 32768 + oc * 64;

    // Phase A: prefetch vv tile to registers (same (gg,q) mapping as C);
    //          stage sW, constants, hn
    float4 vreg[4];
    #pragma unroll
    for (int k = 0; k < 4; k++) {
        int l = tid + k * 512;
        int gg = l >> 4, q = (l & 15) << 2;
        vreg[k] = *(const float4*)(vsrc + gg * 256 + q);
    }
    #pragma unroll
    for (int k = 0; k < 4; k++) {
        int l = tid + k * 512;
        int gg = l >> 4, q = (l & 15) << 2;
        float4 wv = *(const float4*)(wsrc + gg * 256 + q);
        *(float4*)(sW + gg * 64 + q) = wv;
    }
    if (tid < 256) sC2[tid] = g_c2d[tid];
    else if (tid < 384) sC1[tid - 256] = g_c1[tid - 256];
    else if (tid < 448) shn[tid - 384] = g_hn[b * 64 + (tid - 384)];
    __syncthreads();

    // Phase B: u (tid<128) ; Q (tid 128..191)
    if (tid < 128) {
        float acc = g_bba[tid];
        const float4* row = (const float4*)(g_M2 + tid * 64);
        #pragma unroll
        for (int j = 0; j < 16; j++) {
            float4 w4 = row[j];
            float4 x4 = *(const float4*)(shn + 4 * j);
            acc += w4.x * x4.x + w4.y * x4.y + w4.z * x4.z + w4.w * x4.w;
        }
        sU[tid] = acc;
    } else if (tid < 192) {
        int i = tid - 128;
        float s0 = 0.f, s1 = 0.f;
        #pragma unroll 4
        for (int g = 0; g < 128; g += 2) {
            s0 += sC1[g]     * sW[g * 64 + i];
            s1 += sC1[g + 1] * sW[(g + 1) * 64 + i];
        }
        sQ[i] = s0 + s1;
    }
    __syncthreads();

    // Phase C: build sVd = (vv + u) duplicated pairs, from registers
    #pragma unroll
    for (int k = 0; k < 4; k++) {
        int l = tid + k * 512;
        int gg = l >> 4, q = (l & 15) << 2;
        float uu = sU[gg];
        float4 vv = vreg[k];
        vv.x += uu; vv.y += uu; vv.z += uu; vv.w += uu;
        float* vd = sVd + gg * 128 + q * 2;
        ((float4*)vd)[0] = make_float4(vv.x, vv.x, vv.y, vv.y);
        ((float4*)vd)[1] = make_float4(vv.z, vv.z, vv.w, vv.w);
    }
    __syncthreads();

    // Phase D: P (incl. u-part via sVd)
    if (tid < 64) {
        float s0 = 0.f, s1 = 0.f;
        #pragma unroll 4
        for (int g = 0; g < 128; g += 2) {
            s0 += sC1[g]     * sVd[g * 128 + 2 * tid];
            s1 += sC1[g + 1] * sVd[(g + 1) * 128 + 2 * tid];
        }
        sP[tid] = s0 + s1;
    }
    __syncthreads();

    // Phase E: main f32x2 loop, micro-tile 2o x 4i
    const int tx = tid & 15, ty = tid >> 4;   // ty 0..31 -> o = 2*ty
    unsigned long long a00 = 0, a01 = 0, a10 = 0, a11 = 0;
    const float* vbase = sVd + ty * 4;        // dup pair of o=2ty, 2ty+1
    const float* wbase = sW + tx * 4;
    const unsigned long long* c2base = (const unsigned long long*)sC2;
    const unsigned long long MASK = 0x7FFFFFFF7FFFFFFFULL;

    #pragma unroll 8
    for (int gg = 0; gg < 128; gg++) {
        ulonglong2 vp = *(const ulonglong2*)(vbase + gg * 128);
        ulonglong2 wp = *(const ulonglong2*)(wbase + gg * 64);
        unsigned long long c2 = c2base[gg];
        unsigned long long tt;
        tt = addp(vp.x, wp.x) & MASK;  a00 = fmap(c2, tt, a00);
        tt = addp(vp.x, wp.y) & MASK;  a01 = fmap(c2, tt, a01);
        tt = addp(vp.y, wp.x) & MASK;  a10 = fmap(c2, tt, a10);
        tt = addp(vp.y, wp.y) & MASK;  a11 = fmap(c2, tt, a11);
    }

    const float ba2v = ba2p[0];
    float4 q4 = *(const float4*)(sQ + tx * 4);
    unsigned long long acc[2][2] = {{a00, a01}, {a10, a11}};
    #pragma unroll
    for (int r = 0; r < 2; r++) {
        float pr = sP[ty * 2 + r] + ba2v;
        float4 res;
        res.x = plo(acc[r][0]) + pr + q4.x;
        res.y = phi(acc[r][0]) + pr + q4.y;
        res.z = plo(acc[r][1]) + pr + q4.z;
        res.w = phi(acc[r][1]) + pr + q4.w;
        int og = oc * 64 + ty * 2 + r;
        *(float4*)(out + OFF_A + b * 65536 + og * 256 + ic * 64 + tx * 4) = res;
    }
}

// ============================================================
extern "C" void kernel_launch(void* const* d_in, const int* in_sizes, int n_in,
                              void* d_out, int out_size)
{
    const float* ope   = (const float*)d_in[0];
    const float* ins   = (const float*)d_in[1];
    const float* h_in  = (const float*)d_in[2];
    const float* c_in  = (const float*)d_in[3];
    const float* W_ih  = (const float*)d_in[4];
    const float* W_hh  = (const float*)d_in[5];
    const float* b_ih  = (const float*)d_in[6];
    const float* b_hh  = (const float*)d_in[7];
    const float* Wv0   = (const float*)d_in[8];
    const float* bv0   = (const float*)d_in[9];
    const float* Wv1   = (const float*)d_in[10];
    const float* bv1   = (const float*)d_in[11];
    const float* Wv2   = (const float*)d_in[12];
    const float* bv2   = (const float*)d_in[13];
    const float* Wa0   = (const float*)d_in[14];
    const float* ba0   = (const float*)d_in[15];
    const float* Wa1   = (const float*)d_in[16];
    const float* ba1   = (const float*)d_in[17];
    const float* Wa2   = (const float*)d_in[18];
    const float* ba2   = (const float*)d_in[19];
    float* out = (float*)d_out;

    cudaFuncSetAttribute(k_prod, cudaFuncAttributeMaxDynamicSharedMemorySize, 69888);
    cudaFuncSetAttribute(k_cons, cudaFuncAttributeMaxDynamicSharedMemorySize, 101120);

    k_prod<<<145, 256, 69888>>>(ope, ins, h_in, c_in, W_ih, W_hh, b_ih, b_hh,
                                Wa0, ba0, Wa1, ba1, Wa2, out);
    k_cons<<<136, 512, 101120>>>(ba2, Wv0, bv0, Wv1, bv1, Wv2, bv2, out);
}